// round 1
// baseline (speedup 1.0000x reference)
#include <cuda_runtime.h>
#include <cstdint>

#define CRF_B 1024
#define CRF_S 512
#define CRF_T 64

// Device scratch (allowed: static __device__ global, no allocation)
__device__ float g_partial[CRF_B];

__device__ __forceinline__ float ex2f(float x) {
    float y; asm("ex2.approx.ftz.f32 %0, %1;" : "=f"(y) : "f"(x)); return y;
}
__device__ __forceinline__ float lg2f(float x) {
    float y; asm("lg2.approx.f32 %0, %1;" : "=f"(y) : "f"(x)); return y;
}

// One CTA (64 threads) per batch element. Thread j owns state/column j.
// Works in the base-2 log domain: b = log2(e) * alpha.
__global__ void __launch_bounds__(CRF_T) crf_scan_kernel(
    const float* __restrict__ inputs,        // [B, S, T] f32
    const float* __restrict__ trans,         // [T, T] f32
    const unsigned char* __restrict__ masks, // [B, S] bool (all false in this dataset)
    const int* __restrict__ tags)            // [B, S] int32
{
    const int b = blockIdx.x;
    const int j = threadIdx.x;
    const float L = 1.4426950408889634f;  // log2(e)

    __shared__ float p_sh[CRF_T];
    __shared__ float Msh;
    __shared__ float red[CRF_T];
    __shared__ int tag_sh[CRF_S];
    __shared__ unsigned char mask_sh[CRF_S];

    const float* xb = inputs + (size_t)b * CRF_S * CRF_T;
    const int* tg = tags + (size_t)b * CRF_S;
    const unsigned char* mk = masks + (size_t)b * CRF_S;

    // Stage tags + masks for this batch row into shared
    for (int s = j; s < CRF_S; s += CRF_T) {
        tag_sh[s] = tg[s];
        mask_sh[s] = mk[s];
    }
    __syncthreads();

    // unary + binary partial sums (strided over s)
    float ub = 0.f;
    for (int s = j; s < CRF_S; s += CRF_T) {
        if (!mask_sh[s]) {
            ub += xb[s * CRF_T + tag_sh[s]];
            if (s >= 1) ub += trans[tag_sh[s - 1] * CRF_T + tag_sh[s]];
        }
    }

    // E[i] = 2^(log2e * trans[i][j]) — column j of exp(transitions), register-resident
    float E[CRF_T];
#pragma unroll
    for (int i = 0; i < CRF_T; i++)
        E[i] = ex2f(L * trans[i * CRF_T + j]);

    // alpha_0 = inputs[b, 0, :]
    float bj = L * xb[j];
    if (j == 0) Msh = bj;
    __syncthreads();

    float xnext = xb[CRF_T + j];  // prefetch x for t=1

    for (int t = 1; t < CRF_S; t++) {
        float M = Msh;                 // = b_0 from previous step (rescaling anchor)
        p_sh[j] = ex2f(bj - M);        // p_j = 2^(b_j - M)
        float xt = xnext;
        unsigned char m = mask_sh[t];
        __syncthreads();
        if (t + 1 < CRF_S) xnext = xb[(t + 1) * CRF_T + j];  // prefetch next x

        // s_j = sum_i p_i * E_ij  (p broadcast via float4 LDS, E in registers)
        float s0 = 0.f, s1 = 0.f, s2 = 0.f, s3 = 0.f;
        const float4* p4 = reinterpret_cast<const float4*>(p_sh);
#pragma unroll
        for (int i = 0; i < CRF_T / 4; i++) {
            float4 p = p4[i];
            s0 = fmaf(p.x, E[4 * i + 0], s0);
            s1 = fmaf(p.y, E[4 * i + 1], s1);
            s2 = fmaf(p.z, E[4 * i + 2], s2);
            s3 = fmaf(p.w, E[4 * i + 3], s3);
        }
        float ssum = (s0 + s1) + (s2 + s3);

        float bn = fmaf(xt, L, M + lg2f(ssum));  // b'_j = L*x_j + M + log2(s_j)
        if (!m) bj = bn;                          // masked step keeps old alpha
        if (j == 0) Msh = bj;                     // anchor for next step
        __syncthreads();                          // protects p_sh reuse + Msh publish
    }

    // log_norm = logsumexp over final alphas (natural log)
    float M = Msh;
    p_sh[j] = ex2f(bj - M);
    red[j] = ub;
    __syncthreads();
    if (j == 0) {
        float sp = 0.f, su = 0.f;
        for (int i = 0; i < CRF_T; i++) { sp += p_sh[i]; su += red[i]; }
        float log_norm = (M + lg2f(sp)) / L;
        g_partial[b] = -(su - log_norm);   // -log_likelihood for this batch
    }
}

// Deterministic final reduction + transitions passthrough.
__global__ void crf_finalize_kernel(const float* __restrict__ trans,
                                    float* __restrict__ out, int out_size)
{
    const int tid = threadIdx.x;  // 256 threads, single CTA
    __shared__ float acc[256];
    float s = 0.f;
    for (int i = tid; i < CRF_B; i += 256) s += g_partial[i];
    acc[tid] = s;
    __syncthreads();
    for (int w = 128; w > 0; w >>= 1) {
        if (tid < w) acc[tid] += acc[tid + w];
        __syncthreads();
    }
    if (tid == 0) out[0] = acc[0] / (float)CRF_B;
    // transitions passthrough: out[1 .. 1+T*T)
    for (int i = tid; i < CRF_T * CRF_T && (1 + i) < out_size; i += 256)
        out[1 + i] = trans[i];
}

extern "C" void kernel_launch(void* const* d_in, const int* in_sizes, int n_in,
                              void* d_out, int out_size)
{
    const float* inputs = (const float*)d_in[0];
    const float* trans  = (const float*)d_in[1];
    const unsigned char* masks = (const unsigned char*)d_in[2];
    const int* tags = (const int*)d_in[3];
    float* out = (float*)d_out;

    crf_scan_kernel<<<CRF_B, CRF_T>>>(inputs, trans, masks, tags);
    crf_finalize_kernel<<<1, 256>>>(trans, out, out_size);
}